// round 10
// baseline (speedup 1.0000x reference)
#include <cuda_runtime.h>

typedef unsigned long long u64;

#define TW 64
#define TH 28
#define IW 74                   // TW + 10 halo
#define PS 29                   // transposed plane stride (odd)
#define NTHREADS 224            // 7 warps; 6 blocks/SM -> reg cap 48 (natural footprint)

#define IMG_H 768
#define IMG_W 768
#define OUT_H 758
#define OUT_W 758
#define NBATCH 16
#define NCH 3

// smem: sM, sE: [IW][PS] u64 = 34336 B  (6 blocks/SM: 206KB of 228KB)
#define SMEM_BYTES (IW * PS * (8 + 8))

__device__ float g_acc[NBATCH];

// Gaussian(sigma=1.5, win=11)
#define W0 0.00102838f
#define W1 0.00759880f
#define W2 0.03600077f
#define W3 0.10936070f
#define W4 0.21300553f
#define W5 0.26601172f

__device__ __forceinline__ u64 pack2(float lo, float hi) {
    u64 r; asm("mov.b64 %0, {%1,%2};" : "=l"(r) : "f"(lo), "f"(hi)); return r;
}
__device__ __forceinline__ void unpack2(u64 v, float& lo, float& hi) {
    asm("mov.b64 {%0,%1}, %2;" : "=f"(lo), "=f"(hi) : "l"(v));
}
__device__ __forceinline__ u64 fma2(u64 a, u64 b, u64 c) {
    u64 d; asm("fma.rn.f32x2 %0, %1, %2, %3;" : "=l"(d) : "l"(a), "l"(b), "l"(c));
    return d;
}
__device__ __forceinline__ u64 mul2(u64 a, u64 b) {
    u64 d; asm("mul.rn.f32x2 %0, %1, %2;" : "=l"(d) : "l"(a), "l"(b));
    return d;
}
__device__ __forceinline__ u64 add2(u64 a, u64 b) {
    u64 d; asm("add.rn.f32x2 %0, %1, %2;" : "=l"(d) : "l"(a), "l"(b));
    return d;
}

// folded symmetric 11-tap packed chain
__device__ __forceinline__ u64 chain2(const u64* w, int j,
                                      u64 c0, u64 c1, u64 c2, u64 c3, u64 c4, u64 c5) {
    u64 acc = mul2(c5, w[j + 5]);
    acc = fma2(c4, add2(w[j + 4], w[j + 6]), acc);
    acc = fma2(c3, add2(w[j + 3], w[j + 7]), acc);
    acc = fma2(c2, add2(w[j + 2], w[j + 8]), acc);
    acc = fma2(c1, add2(w[j + 1], w[j + 9]), acc);
    acc = fma2(c0, add2(w[j],     w[j + 10]), acc);
    return acc;
}

__global__ void ssim_zero_kernel() {
    if (threadIdx.x < NBATCH) g_acc[threadIdx.x] = 0.0f;
}
__global__ void ssim_dummy1_kernel() {}
__global__ void ssim_dummy2_kernel() {}
__global__ void ssim_dummy3_kernel() {}

__global__ void ssim_finalize_kernel(float* __restrict__ out) {
    if (threadIdx.x < NBATCH)
        out[threadIdx.x] = g_acc[threadIdx.x] *
            (1.0f / (float)(NCH * OUT_H * OUT_W));
}

template <bool EDGE>
__device__ __forceinline__ float ssim_tile(const float* __restrict__ Xp,
                                           const float* __restrict__ Yp,
                                           u64* sM, u64* sE,
                                           int ox0, int oy0, int tid) {
    const u64 C0p = pack2(W0, W0), C1p = pack2(W1, W1), C2p = pack2(W2, W2);
    const u64 C3p = pack2(W3, W3), C4p = pack2(W4, W4), C5p = pack2(W5, W5);

    // ---- pass 1: VERTICAL blur in (s,d)=(x+y, x-y) basis -> transposed planes ----
    // task: column c, 4 output rows from r0.  IW*(TH/4) = 518 tasks.
    for (int t = tid; t < IW * (TH / 4); t += NTHREADS) {
        int c  = t % IW;
        int r0 = (t / IW) * 4;

        u64 w[14];
        if (EDGE) {
            int gx = min(ox0 + c, IMG_W - 1);   // clamp: OOB feeds discarded outputs only
            #pragma unroll
            for (int i = 0; i < 14; i++) {
                int gy = min(oy0 + r0 + i, IMG_H - 1);
                int g = gy * IMG_W + gx;
                float xv = __ldg(Xp + g), yv = __ldg(Yp + g);
                w[i] = pack2(xv + yv, xv - yv);
            }
        } else {
            int g = (oy0 + r0) * IMG_W + (ox0 + c);
            #pragma unroll
            for (int i = 0; i < 14; i++) {
                float xv = __ldg(Xp + g), yv = __ldg(Yp + g);
                w[i] = pack2(xv + yv, xv - yv);
                g += IMG_W;
            }
        }

        // M stream (mu_s, mu_d)
        #pragma unroll
        for (int j = 0; j < 4; j++)
            sM[c * PS + r0 + j] = chain2(w, j, C0p, C1p, C2p, C3p, C4p, C5p);

        // squares in place: (s^2, d^2)
        #pragma unroll
        for (int i = 0; i < 14; i++) w[i] = mul2(w[i], w[i]);

        // E stream (E[s^2], E[d^2])
        #pragma unroll
        for (int j = 0; j < 4; j++)
            sE[c * PS + r0 + j] = chain2(w, j, C0p, C1p, C2p, C3p, C4p, C5p);
    }
    __syncthreads();

    // ---- pass 2: HORIZONTAL blur on transposed planes + SSIM ----
    // task: output row r (0..TH-1), 4 output cols from c0. TH*16 = 448 = 2*NTHREADS.
    const float K1 = 0.0001f;        // C1
    const float K2 = 0.0009f;        // C2
    const float EPSV = 1e-8f;

    float lsum = 0.0f;
    #pragma unroll
    for (int it = 0; it < 2; it++) {
        int t  = tid + it * NTHREADS;
        int r  = t % TH;
        int c0 = (t / TH) * 4;

        u64 win[14];
        u64 mu[4], ee[4];

        #pragma unroll
        for (int i = 0; i < 14; i++) win[i] = sM[(c0 + i) * PS + r];
        #pragma unroll
        for (int j = 0; j < 4; j++)
            mu[j] = chain2(win, j, C0p, C1p, C2p, C3p, C4p, C5p);

        #pragma unroll
        for (int i = 0; i < 14; i++) win[i] = sE[(c0 + i) * PS + r];
        #pragma unroll
        for (int j = 0; j < 4; j++)
            ee[j] = chain2(win, j, C0p, C1p, C2p, C3p, C4p, C5p);

        const int oy = oy0 + r;
        #pragma unroll
        for (int j = 0; j < 4; j++) {
            bool ok = true;
            if (EDGE) {
                int ox = ox0 + c0 + j;
                ok = (oy < OUT_H) && (ox < OUT_W);
            }
            if (ok) {
                // mu = (mu_s, mu_d), ee = (E[s^2], E[d^2])
                u64 p2 = mul2(mu[j], mu[j]);
                float q, rr; unpack2(p2, q, rr);     // q = mu_s^2, rr = mu_d^2
                float es, ed; unpack2(ee[j], es, ed);
                float a = es - q;                    // var(s) >= 0
                float bq = ed - rr;                  // var(d) >= 0
                // 2vxy+C2 = (a-b)/2+C2 ; vx+vy+C2 = (a+b)/2+C2
                // 2 mx my + C1 = (q-r)/2+C1 ; mx^2+my^2+C1 = (q+r)/2+C1
                float num_cs = fmaf(0.5f, a - bq, K2);
                float den_cs = fmaf(0.5f, a + bq, K2 + EPSV);
                float num_l  = fmaf(0.5f, q - rr, K1);
                float den_l  = fmaf(0.5f, q + rr, K1 + EPSV);
                // l > 0 always: relu(cs)*l == relu(l*cs) -> single divide
                lsum += fmaxf(__fdividef(num_cs * num_l, den_cs * den_l), 0.0f);
            }
        }
    }
    return lsum;
}

__global__ __launch_bounds__(NTHREADS, 6)
void ssim_main_kernel(const float* __restrict__ X, const float* __restrict__ Y) {
    extern __shared__ __align__(16) unsigned char smem_raw[];
    u64* sM = (u64*)smem_raw;        // [IW][PS] packed (mu_s, mu_d)
    u64* sE = sM + IW * PS;          // [IW][PS] packed (E[s^2], E[d^2])

    const int tid = threadIdx.x;
    const int img = blockIdx.z;              // b*3 + ch
    const int b = img / NCH;
    const int ox0 = blockIdx.x * TW;
    const int oy0 = blockIdx.y * TH;
    const float* Xp = X + (size_t)img * IMG_H * IMG_W;
    const float* Yp = Y + (size_t)img * IMG_H * IMG_W;

    const bool edge = (blockIdx.x == gridDim.x - 1) || (blockIdx.y == gridDim.y - 1);
    float lsum = edge ? ssim_tile<true >(Xp, Yp, sM, sE, ox0, oy0, tid)
                      : ssim_tile<false>(Xp, Yp, sM, sE, ox0, oy0, tid);

    // ---- block reduction ----
    #pragma unroll
    for (int off = 16; off > 0; off >>= 1)
        lsum += __shfl_down_sync(0xffffffffu, lsum, off);

    float* red = (float*)smem_raw;   // aliases sM (dead after pass 2)
    int lane = tid & 31, wid = tid >> 5;
    __syncthreads();
    if (lane == 0) red[wid] = lsum;
    __syncthreads();
    if (tid == 0) {
        float s = 0.f;
        #pragma unroll
        for (int i = 0; i < NTHREADS / 32; i++) s += red[i];
        atomicAdd(&g_acc[b], s);
    }
}

extern "C" void kernel_launch(void* const* d_in, const int* in_sizes, int n_in,
                              void* d_out, int out_size) {
    const float* X = (const float*)d_in[0];
    const float* Y = (const float*)d_in[1];
    (void)in_sizes; (void)n_in; (void)out_size;

    cudaFuncSetAttribute(ssim_main_kernel,
                         cudaFuncAttributeMaxDynamicSharedMemorySize,
                         SMEM_BYTES);

    // keep main at launch position 3 (ncu capture lands there)
    ssim_zero_kernel<<<1, 32>>>();       // 0
    ssim_dummy1_kernel<<<1, 32>>>();     // 1
    ssim_dummy2_kernel<<<1, 32>>>();     // 2
    dim3 grid((OUT_W + TW - 1) / TW,     // 12
              (OUT_H + TH - 1) / TH,     // 28
              NBATCH * NCH);             // 48
    ssim_main_kernel<<<grid, NTHREADS, SMEM_BYTES>>>(X, Y);  // 3
    ssim_finalize_kernel<<<1, 32>>>((float*)d_out);          // 4
    ssim_dummy3_kernel<<<1, 32>>>();     // 5
}

// round 11
// speedup vs baseline: 1.4068x; 1.4068x over previous
#include <cuda_runtime.h>

typedef unsigned long long u64;

#define TW 64
#define TH 32
#define IW 74                   // TW + 10 halo
#define PS 33                   // transposed plane stride (odd)
#define NTHREADS 256

#define IMG_H 768
#define IMG_W 768
#define OUT_H 758
#define OUT_W 758
#define NBATCH 16
#define NCH 3

// smem: sM, sE: [IW][PS] u64 = 39072 B  (5 blocks/SM)
#define SMEM_BYTES (IW * PS * (8 + 8))

__device__ float g_acc[NBATCH];

// Gaussian(sigma=1.5, win=11)
#define W0 0.00102838f
#define W1 0.00759880f
#define W2 0.03600077f
#define W3 0.10936070f
#define W4 0.21300553f
#define W5 0.26601172f

__device__ __forceinline__ u64 pack2(float lo, float hi) {
    u64 r; asm("mov.b64 %0, {%1,%2};" : "=l"(r) : "f"(lo), "f"(hi)); return r;
}
__device__ __forceinline__ void unpack2(u64 v, float& lo, float& hi) {
    asm("mov.b64 {%0,%1}, %2;" : "=f"(lo), "=f"(hi) : "l"(v));
}
__device__ __forceinline__ u64 fma2(u64 a, u64 b, u64 c) {
    u64 d; asm("fma.rn.f32x2 %0, %1, %2, %3;" : "=l"(d) : "l"(a), "l"(b), "l"(c));
    return d;
}
__device__ __forceinline__ u64 mul2(u64 a, u64 b) {
    u64 d; asm("mul.rn.f32x2 %0, %1, %2;" : "=l"(d) : "l"(a), "l"(b));
    return d;
}
__device__ __forceinline__ u64 add2(u64 a, u64 b) {
    u64 d; asm("add.rn.f32x2 %0, %1, %2;" : "=l"(d) : "l"(a), "l"(b));
    return d;
}

// folded symmetric 11-tap packed chain
__device__ __forceinline__ u64 chain2(const u64* w, int j,
                                      u64 c0, u64 c1, u64 c2, u64 c3, u64 c4, u64 c5) {
    u64 acc = mul2(c5, w[j + 5]);
    acc = fma2(c4, add2(w[j + 4], w[j + 6]), acc);
    acc = fma2(c3, add2(w[j + 3], w[j + 7]), acc);
    acc = fma2(c2, add2(w[j + 2], w[j + 8]), acc);
    acc = fma2(c1, add2(w[j + 1], w[j + 9]), acc);
    acc = fma2(c0, add2(w[j],     w[j + 10]), acc);
    return acc;
}

__global__ void ssim_zero_kernel() {
    if (threadIdx.x < NBATCH) g_acc[threadIdx.x] = 0.0f;
}
__global__ void ssim_dummy1_kernel() {}
__global__ void ssim_dummy2_kernel() {}
__global__ void ssim_dummy3_kernel() {}

__global__ void ssim_finalize_kernel(float* __restrict__ out) {
    if (threadIdx.x < NBATCH)
        out[threadIdx.x] = g_acc[threadIdx.x] *
            (1.0f / (float)(NCH * OUT_H * OUT_W));
}

template <bool EDGE>
__device__ __forceinline__ float ssim_tile(const float* __restrict__ Xp,
                                           const float* __restrict__ Yp,
                                           u64* sM, u64* sE,
                                           int ox0, int oy0, int tid) {
    const u64 C0p = pack2(W0, W0), C1p = pack2(W1, W1), C2p = pack2(W2, W2);
    const u64 C3p = pack2(W3, W3), C4p = pack2(W4, W4), C5p = pack2(W5, W5);

    // ---- pass 1: VERTICAL blur in (s,d)=(x+y, x-y) basis -> transposed planes ----
    // task: column c, 4 output rows from r0.  IW*8 = 592 tasks.
    for (int t = tid; t < IW * 8; t += NTHREADS) {
        int c  = t % IW;
        int r0 = (t / IW) * 4;

        u64 w[14];
        if (EDGE) {
            int gx = min(ox0 + c, IMG_W - 1);   // clamp: OOB feeds discarded outputs only
            #pragma unroll
            for (int i = 0; i < 14; i++) {
                int gy = min(oy0 + r0 + i, IMG_H - 1);
                int g = gy * IMG_W + gx;
                float xv = __ldg(Xp + g), yv = __ldg(Yp + g);
                w[i] = pack2(xv + yv, xv - yv);
            }
        } else {
            int g = (oy0 + r0) * IMG_W + (ox0 + c);
            #pragma unroll
            for (int i = 0; i < 14; i++) {
                float xv = __ldg(Xp + g), yv = __ldg(Yp + g);
                w[i] = pack2(xv + yv, xv - yv);
                g += IMG_W;
            }
        }

        // M stream (mu_s, mu_d)
        #pragma unroll
        for (int j = 0; j < 4; j++)
            sM[c * PS + r0 + j] = chain2(w, j, C0p, C1p, C2p, C3p, C4p, C5p);

        // squares in place: (s^2, d^2)
        #pragma unroll
        for (int i = 0; i < 14; i++) w[i] = mul2(w[i], w[i]);

        // E stream (E[s^2], E[d^2])
        #pragma unroll
        for (int j = 0; j < 4; j++)
            sE[c * PS + r0 + j] = chain2(w, j, C0p, C1p, C2p, C3p, C4p, C5p);
    }
    __syncthreads();

    // ---- pass 2: HORIZONTAL blur on transposed planes + SSIM ----
    // task: output row r (0..31), 4 output cols from c0. 32*16 = 512 = 2*NTHREADS.
    const float K1 = 0.0001f;        // C1
    const float K2 = 0.0009f;        // C2
    const float EPSV = 1e-8f;

    float lsum = 0.0f;
    #pragma unroll
    for (int it = 0; it < 2; it++) {
        int t  = tid + it * NTHREADS;
        int r  = t & 31;
        int c0 = (t >> 5) * 4;

        u64 win[14];
        u64 mu[4], ee[4];

        #pragma unroll
        for (int i = 0; i < 14; i++) win[i] = sM[(c0 + i) * PS + r];
        #pragma unroll
        for (int j = 0; j < 4; j++)
            mu[j] = chain2(win, j, C0p, C1p, C2p, C3p, C4p, C5p);

        #pragma unroll
        for (int i = 0; i < 14; i++) win[i] = sE[(c0 + i) * PS + r];
        #pragma unroll
        for (int j = 0; j < 4; j++)
            ee[j] = chain2(win, j, C0p, C1p, C2p, C3p, C4p, C5p);

        const int oy = oy0 + r;
        #pragma unroll
        for (int j = 0; j < 4; j++) {
            bool ok = true;
            if (EDGE) {
                int ox = ox0 + c0 + j;
                ok = (oy < OUT_H) && (ox < OUT_W);
            }
            if (ok) {
                // mu = (mu_s, mu_d), ee = (E[s^2], E[d^2])
                u64 p2 = mul2(mu[j], mu[j]);
                float q, rr; unpack2(p2, q, rr);     // q = mu_s^2, rr = mu_d^2
                float es, ed; unpack2(ee[j], es, ed);
                float a  = es - q;                   // var(s) = vx+vy+2vxy >= 0
                float bq = ed - rr;                  // var(d) = vx+vy-2vxy >= 0
                // 2vxy+C2 = (a-b)/2+C2 ; vx+vy+C2+eps = (a+b)/2+C2+eps
                // 2mxmy+C1 = (q-r)/2+C1 ; mx^2+my^2+C1+eps = (q+r)/2+C1+eps
                float num_cs = fmaf(0.5f, a - bq, K2);
                float den_cs = fmaf(0.5f, a + bq, K2 + EPSV);
                float num_l  = fmaf(0.5f, q - rr, K1);
                float den_l  = fmaf(0.5f, q + rr, K1 + EPSV);
                // l > 0 always: relu(cs)*l == relu(l*cs) -> single divide
                lsum += fmaxf(__fdividef(num_cs * num_l, den_cs * den_l), 0.0f);
            }
        }
    }
    return lsum;
}

__global__ __launch_bounds__(NTHREADS, 5)
void ssim_main_kernel(const float* __restrict__ X, const float* __restrict__ Y) {
    extern __shared__ __align__(16) unsigned char smem_raw[];
    u64* sM = (u64*)smem_raw;        // [IW][PS] packed (mu_s, mu_d)
    u64* sE = sM + IW * PS;          // [IW][PS] packed (E[s^2], E[d^2])

    const int tid = threadIdx.x;
    const int img = blockIdx.z;              // b*3 + ch
    const int b = img / NCH;
    const int ox0 = blockIdx.x * TW;
    const int oy0 = blockIdx.y * TH;
    const float* Xp = X + (size_t)img * IMG_H * IMG_W;
    const float* Yp = Y + (size_t)img * IMG_H * IMG_W;

    const bool edge = (blockIdx.x == gridDim.x - 1) || (blockIdx.y == gridDim.y - 1);
    float lsum = edge ? ssim_tile<true >(Xp, Yp, sM, sE, ox0, oy0, tid)
                      : ssim_tile<false>(Xp, Yp, sM, sE, ox0, oy0, tid);

    // ---- block reduction ----
    #pragma unroll
    for (int off = 16; off > 0; off >>= 1)
        lsum += __shfl_down_sync(0xffffffffu, lsum, off);

    float* red = (float*)smem_raw;   // aliases sM (dead after pass 2)
    int lane = tid & 31, wid = tid >> 5;
    __syncthreads();
    if (lane == 0) red[wid] = lsum;
    __syncthreads();
    if (tid == 0) {
        float s = 0.f;
        #pragma unroll
        for (int i = 0; i < NTHREADS / 32; i++) s += red[i];
        atomicAdd(&g_acc[b], s);
    }
}

extern "C" void kernel_launch(void* const* d_in, const int* in_sizes, int n_in,
                              void* d_out, int out_size) {
    const float* X = (const float*)d_in[0];
    const float* Y = (const float*)d_in[1];
    (void)in_sizes; (void)n_in; (void)out_size;

    cudaFuncSetAttribute(ssim_main_kernel,
                         cudaFuncAttributeMaxDynamicSharedMemorySize,
                         SMEM_BYTES);

    // keep main at launch position 3 (ncu capture lands there)
    ssim_zero_kernel<<<1, 32>>>();       // 0
    ssim_dummy1_kernel<<<1, 32>>>();     // 1
    ssim_dummy2_kernel<<<1, 32>>>();     // 2
    dim3 grid((OUT_W + TW - 1) / TW,     // 12
              (OUT_H + TH - 1) / TH,     // 24
              NBATCH * NCH);             // 48
    ssim_main_kernel<<<grid, NTHREADS, SMEM_BYTES>>>(X, Y);  // 3
    ssim_finalize_kernel<<<1, 32>>>((float*)d_out);          // 4
    ssim_dummy3_kernel<<<1, 32>>>();     // 5
}

// round 12
// speedup vs baseline: 1.5287x; 1.0867x over previous
#include <cuda_runtime.h>

typedef unsigned long long u64;

#define TW 64
#define TH 32
#define IW 74                   // TW + 10 halo
#define PS 33                   // transposed plane stride (odd)
#define NTHREADS 256

#define IMG_H 768
#define IMG_W 768
#define OUT_H 758
#define OUT_W 758
#define NBATCH 16
#define NCH 3

// smem: sM, sE: [IW][PS] u64 = 39072 B
#define SMEM_BYTES (IW * PS * (8 + 8))

__device__ float g_acc[NBATCH];

// Gaussian(sigma=1.5, win=11)
#define W0 0.00102838f
#define W1 0.00759880f
#define W2 0.03600077f
#define W3 0.10936070f
#define W4 0.21300553f
#define W5 0.26601172f

__device__ __forceinline__ u64 pack2(float lo, float hi) {
    u64 r; asm("mov.b64 %0, {%1,%2};" : "=l"(r) : "f"(lo), "f"(hi)); return r;
}
__device__ __forceinline__ void unpack2(u64 v, float& lo, float& hi) {
    asm("mov.b64 {%0,%1}, %2;" : "=f"(lo), "=f"(hi) : "l"(v));
}
__device__ __forceinline__ u64 fma2(u64 a, u64 b, u64 c) {
    u64 d; asm("fma.rn.f32x2 %0, %1, %2, %3;" : "=l"(d) : "l"(a), "l"(b), "l"(c));
    return d;
}
__device__ __forceinline__ u64 mul2(u64 a, u64 b) {
    u64 d; asm("mul.rn.f32x2 %0, %1, %2;" : "=l"(d) : "l"(a), "l"(b));
    return d;
}
__device__ __forceinline__ u64 add2(u64 a, u64 b) {
    u64 d; asm("add.rn.f32x2 %0, %1, %2;" : "=l"(d) : "l"(a), "l"(b));
    return d;
}

// folded symmetric 11-tap packed chain
#define CHAIN2(w, j) ({                                        \
    u64 acc_ = mul2(C5p, (w)[(j) + 5]);                        \
    acc_ = fma2(C4p, add2((w)[(j) + 4], (w)[(j) + 6]), acc_);  \
    acc_ = fma2(C3p, add2((w)[(j) + 3], (w)[(j) + 7]), acc_);  \
    acc_ = fma2(C2p, add2((w)[(j) + 2], (w)[(j) + 8]), acc_);  \
    acc_ = fma2(C1p, add2((w)[(j) + 1], (w)[(j) + 9]), acc_);  \
    acc_ = fma2(C0p, add2((w)[(j)],     (w)[(j) + 10]), acc_); \
    acc_; })

__global__ void ssim_zero_kernel() {
    if (threadIdx.x < NBATCH) g_acc[threadIdx.x] = 0.0f;
}
__global__ void ssim_dummy1_kernel() {}
__global__ void ssim_dummy2_kernel() {}
__global__ void ssim_dummy3_kernel() {}

__global__ void ssim_finalize_kernel(float* __restrict__ out) {
    if (threadIdx.x < NBATCH)
        out[threadIdx.x] = g_acc[threadIdx.x] *
            (1.0f / (float)(NCH * OUT_H * OUT_W));
}

template <bool EDGE>
__device__ __forceinline__ float ssim_tile(const float* __restrict__ Xp,
                                           const float* __restrict__ Yp,
                                           u64* sM, u64* sE,
                                           int ox0, int oy0, int tid) {
    const u64 C0p = pack2(W0, W0), C1p = pack2(W1, W1), C2p = pack2(W2, W2);
    const u64 C3p = pack2(W3, W3), C4p = pack2(W4, W4), C5p = pack2(W5, W5);

    // ---- pass 1: VERTICAL blur in (s,d)=(x+y, x-y) basis -> transposed planes ----
    // (identical to R11)  task: column c, 4 output rows from r0. IW*8 = 592 tasks.
    for (int t = tid; t < IW * 8; t += NTHREADS) {
        int c  = t % IW;
        int r0 = (t / IW) * 4;

        u64 w[14];
        if (EDGE) {
            int gx = min(ox0 + c, IMG_W - 1);   // clamp: OOB feeds discarded outputs only
            #pragma unroll
            for (int i = 0; i < 14; i++) {
                int gy = min(oy0 + r0 + i, IMG_H - 1);
                int g = gy * IMG_W + gx;
                float xv = __ldg(Xp + g), yv = __ldg(Yp + g);
                w[i] = pack2(xv + yv, xv - yv);
            }
        } else {
            int g = (oy0 + r0) * IMG_W + (ox0 + c);
            #pragma unroll
            for (int i = 0; i < 14; i++) {
                float xv = __ldg(Xp + g), yv = __ldg(Yp + g);
                w[i] = pack2(xv + yv, xv - yv);
                g += IMG_W;
            }
        }

        // M stream (mu_s, mu_d)
        #pragma unroll
        for (int j = 0; j < 4; j++)
            sM[c * PS + r0 + j] = CHAIN2(w, j);

        // squares in place: (s^2, d^2)
        #pragma unroll
        for (int i = 0; i < 14; i++) w[i] = mul2(w[i], w[i]);

        // E stream (E[s^2], E[d^2])
        #pragma unroll
        for (int j = 0; j < 4; j++)
            sE[c * PS + r0 + j] = CHAIN2(w, j);
    }
    __syncthreads();

    // ---- pass 2: HORIZONTAL blur, stream-sequential, 8 outputs/thread ----
    // 256 tasks exactly: r = tid&31 (0..31), c0 = (tid>>5)*8 (0..56).
    const float K1 = 0.0001f;        // C1
    const float K2 = 0.0009f;        // C2
    const float EPSV = 1e-8f;

    const int r  = tid & 31;
    const int c0 = (tid >> 5) * 8;

    u64 win[18];
    float q[8], rr[8];               // mu_s^2, mu_d^2 per output

    // --- M phase: window loads interleaved with chain computes ---
    #pragma unroll
    for (int i = 0; i < 11; i++) win[i] = sM[(c0 + i) * PS + r];
    #pragma unroll
    for (int j = 0; j < 8; j++) {
        if (j > 0) win[j + 10] = sM[(c0 + j + 10) * PS + r];
        u64 mu = CHAIN2(win, j);
        u64 p2 = mul2(mu, mu);
        unpack2(p2, q[j], rr[j]);
    }

    // --- E phase: reuse window registers ---
    #pragma unroll
    for (int i = 0; i < 11; i++) win[i] = sE[(c0 + i) * PS + r];

    const int oy = oy0 + r;
    float lsum = 0.0f;
    #pragma unroll
    for (int j = 0; j < 8; j++) {
        if (j > 0) win[j + 10] = sE[(c0 + j + 10) * PS + r];
        u64 ee = CHAIN2(win, j);

        bool ok = true;
        if (EDGE) {
            int ox = ox0 + c0 + j;
            ok = (oy < OUT_H) && (ox < OUT_W);
        }
        if (ok) {
            float es, ed; unpack2(ee, es, ed);
            float a  = es - q[j];            // var(s) = vx+vy+2vxy >= 0
            float bq = ed - rr[j];           // var(d) = vx+vy-2vxy >= 0
            float num_cs = fmaf(0.5f, a - bq, K2);
            float den_cs = fmaf(0.5f, a + bq, K2 + EPSV);
            float num_l  = fmaf(0.5f, q[j] - rr[j], K1);
            float den_l  = fmaf(0.5f, q[j] + rr[j], K1 + EPSV);
            // l > 0 always: relu(cs)*l == relu(l*cs) -> single divide
            lsum += fmaxf(__fdividef(num_cs * num_l, den_cs * den_l), 0.0f);
        }
    }
    return lsum;
}

__global__ __launch_bounds__(NTHREADS, 4)
void ssim_main_kernel(const float* __restrict__ X, const float* __restrict__ Y) {
    extern __shared__ __align__(16) unsigned char smem_raw[];
    u64* sM = (u64*)smem_raw;        // [IW][PS] packed (mu_s, mu_d)
    u64* sE = sM + IW * PS;          // [IW][PS] packed (E[s^2], E[d^2])

    const int tid = threadIdx.x;
    const int img = blockIdx.z;              // b*3 + ch
    const int b = img / NCH;
    const int ox0 = blockIdx.x * TW;
    const int oy0 = blockIdx.y * TH;
    const float* Xp = X + (size_t)img * IMG_H * IMG_W;
    const float* Yp = Y + (size_t)img * IMG_H * IMG_W;

    const bool edge = (blockIdx.x == gridDim.x - 1) || (blockIdx.y == gridDim.y - 1);
    float lsum = edge ? ssim_tile<true >(Xp, Yp, sM, sE, ox0, oy0, tid)
                      : ssim_tile<false>(Xp, Yp, sM, sE, ox0, oy0, tid);

    // ---- block reduction ----
    #pragma unroll
    for (int off = 16; off > 0; off >>= 1)
        lsum += __shfl_down_sync(0xffffffffu, lsum, off);

    float* red = (float*)smem_raw;   // aliases sM (dead after pass 2)
    int lane = tid & 31, wid = tid >> 5;
    __syncthreads();
    if (lane == 0) red[wid] = lsum;
    __syncthreads();
    if (tid == 0) {
        float s = 0.f;
        #pragma unroll
        for (int i = 0; i < NTHREADS / 32; i++) s += red[i];
        atomicAdd(&g_acc[b], s);
    }
}

extern "C" void kernel_launch(void* const* d_in, const int* in_sizes, int n_in,
                              void* d_out, int out_size) {
    const float* X = (const float*)d_in[0];
    const float* Y = (const float*)d_in[1];
    (void)in_sizes; (void)n_in; (void)out_size;

    cudaFuncSetAttribute(ssim_main_kernel,
                         cudaFuncAttributeMaxDynamicSharedMemorySize,
                         SMEM_BYTES);

    // keep main at launch position 3 (ncu capture lands there)
    ssim_zero_kernel<<<1, 32>>>();       // 0
    ssim_dummy1_kernel<<<1, 32>>>();     // 1
    ssim_dummy2_kernel<<<1, 32>>>();     // 2
    dim3 grid((OUT_W + TW - 1) / TW,     // 12
              (OUT_H + TH - 1) / TH,     // 24
              NBATCH * NCH);             // 48
    ssim_main_kernel<<<grid, NTHREADS, SMEM_BYTES>>>(X, Y);  // 3
    ssim_finalize_kernel<<<1, 32>>>((float*)d_out);          // 4
    ssim_dummy3_kernel<<<1, 32>>>();     // 5
}

// round 13
// speedup vs baseline: 1.6685x; 1.0914x over previous
#include <cuda_runtime.h>

typedef unsigned long long u64;

#define TW 64
#define TH 32
#define IW 74                   // TW + 10 halo
#define PS 33                   // transposed plane stride (odd)
#define NTHREADS 256

#define IMG_H 768
#define IMG_W 768
#define OUT_H 758
#define OUT_W 758
#define NBATCH 16
#define NCH 3

// smem: sM, sE: [IW][PS] u64 = 39072 B
#define SMEM_BYTES (IW * PS * (8 + 8))

__device__ float g_acc[NBATCH];

// Gaussian(sigma=1.5, win=11)
#define W0 0.00102838f
#define W1 0.00759880f
#define W2 0.03600077f
#define W3 0.10936070f
#define W4 0.21300553f
#define W5 0.26601172f

__device__ __forceinline__ u64 pack2(float lo, float hi) {
    u64 r; asm("mov.b64 %0, {%1,%2};" : "=l"(r) : "f"(lo), "f"(hi)); return r;
}
__device__ __forceinline__ void unpack2(u64 v, float& lo, float& hi) {
    asm("mov.b64 {%0,%1}, %2;" : "=f"(lo), "=f"(hi) : "l"(v));
}
__device__ __forceinline__ u64 fma2(u64 a, u64 b, u64 c) {
    u64 d; asm("fma.rn.f32x2 %0, %1, %2, %3;" : "=l"(d) : "l"(a), "l"(b), "l"(c));
    return d;
}
__device__ __forceinline__ u64 mul2(u64 a, u64 b) {
    u64 d; asm("mul.rn.f32x2 %0, %1, %2;" : "=l"(d) : "l"(a), "l"(b));
    return d;
}
__device__ __forceinline__ u64 add2(u64 a, u64 b) {
    u64 d; asm("add.rn.f32x2 %0, %1, %2;" : "=l"(d) : "l"(a), "l"(b));
    return d;
}

// folded symmetric 11-tap packed chain
#define CHAIN2(w, j) ({                                        \
    u64 acc_ = mul2(C5p, (w)[(j) + 5]);                        \
    acc_ = fma2(C4p, add2((w)[(j) + 4], (w)[(j) + 6]), acc_);  \
    acc_ = fma2(C3p, add2((w)[(j) + 3], (w)[(j) + 7]), acc_);  \
    acc_ = fma2(C2p, add2((w)[(j) + 2], (w)[(j) + 8]), acc_);  \
    acc_ = fma2(C1p, add2((w)[(j) + 1], (w)[(j) + 9]), acc_);  \
    acc_ = fma2(C0p, add2((w)[(j)],     (w)[(j) + 10]), acc_); \
    acc_; })

__global__ void ssim_zero_kernel() {
    if (threadIdx.x < NBATCH) g_acc[threadIdx.x] = 0.0f;
}
__global__ void ssim_dummy1_kernel() {}
__global__ void ssim_dummy2_kernel() {}
__global__ void ssim_dummy3_kernel() {}

__global__ void ssim_finalize_kernel(float* __restrict__ out) {
    if (threadIdx.x < NBATCH)
        out[threadIdx.x] = g_acc[threadIdx.x] *
            (1.0f / (float)(NCH * OUT_H * OUT_W));
}

template <bool EDGE>
__device__ __forceinline__ float ssim_tile(const float* __restrict__ Xp,
                                           const float* __restrict__ Yp,
                                           u64* sM, u64* sE,
                                           int ox0, int oy0, int tid) {
    const u64 C0p = pack2(W0, W0), C1p = pack2(W1, W1), C2p = pack2(W2, W2);
    const u64 C3p = pack2(W3, W3), C4p = pack2(W4, W4), C5p = pack2(W5, W5);

    // ---- pass 1: VERTICAL blur in (s,d)=(x+y, x-y) basis, 8 outputs/task ----
    // task: column c, 8 output rows from r0.  IW*(TH/8) = 296 tasks.
    for (int t = tid; t < IW * (TH / 8); t += NTHREADS) {
        int c  = t % IW;
        int r0 = (t / IW) * 8;

        u64 w[18];
        if (EDGE) {
            int gx = min(ox0 + c, IMG_W - 1);   // clamp: OOB feeds discarded outputs only
            #pragma unroll
            for (int i = 0; i < 18; i++) {
                int gy = min(oy0 + r0 + i, IMG_H - 1);
                int g = gy * IMG_W + gx;
                float xv = __ldg(Xp + g), yv = __ldg(Yp + g);
                w[i] = pack2(xv + yv, xv - yv);
            }
        } else {
            int g = (oy0 + r0) * IMG_W + (ox0 + c);
            #pragma unroll
            for (int i = 0; i < 18; i++) {
                float xv = __ldg(Xp + g), yv = __ldg(Yp + g);
                w[i] = pack2(xv + yv, xv - yv);
                g += IMG_W;
            }
        }

        // M stream (mu_s, mu_d)
        #pragma unroll
        for (int j = 0; j < 8; j++)
            sM[c * PS + r0 + j] = CHAIN2(w, j);

        // squares in place: (s^2, d^2)
        #pragma unroll
        for (int i = 0; i < 18; i++) w[i] = mul2(w[i], w[i]);

        // E stream (E[s^2], E[d^2])
        #pragma unroll
        for (int j = 0; j < 8; j++)
            sE[c * PS + r0 + j] = CHAIN2(w, j);
    }
    __syncthreads();

    // ---- pass 2: HORIZONTAL blur, stream-sequential, 8 outputs/thread ----
    // 256 tasks exactly: r = tid&31 (0..31), c0 = (tid>>5)*8 (0..56).
    const float K1 = 0.0001f;        // C1
    const float K2 = 0.0009f;        // C2
    const float EPSV = 1e-8f;

    const int r  = tid & 31;
    const int c0 = (tid >> 5) * 8;

    u64 win[18];
    float q[8], rr[8];               // mu_s^2, mu_d^2 per output

    // --- M phase: window loads interleaved with chain computes ---
    #pragma unroll
    for (int i = 0; i < 11; i++) win[i] = sM[(c0 + i) * PS + r];
    #pragma unroll
    for (int j = 0; j < 8; j++) {
        if (j > 0) win[j + 10] = sM[(c0 + j + 10) * PS + r];
        u64 mu = CHAIN2(win, j);
        u64 p2 = mul2(mu, mu);
        unpack2(p2, q[j], rr[j]);
    }

    // --- E phase: reuse window registers ---
    #pragma unroll
    for (int i = 0; i < 11; i++) win[i] = sE[(c0 + i) * PS + r];

    const int oy = oy0 + r;
    float lsum = 0.0f;
    #pragma unroll
    for (int j = 0; j < 8; j++) {
        if (j > 0) win[j + 10] = sE[(c0 + j + 10) * PS + r];
        u64 ee = CHAIN2(win, j);

        bool ok = true;
        if (EDGE) {
            int ox = ox0 + c0 + j;
            ok = (oy < OUT_H) && (ox < OUT_W);
        }
        if (ok) {
            float es, ed; unpack2(ee, es, ed);
            float a  = es - q[j];            // var(s) = vx+vy+2vxy >= 0
            float bq = ed - rr[j];           // var(d) = vx+vy-2vxy >= 0
            float num_cs = fmaf(0.5f, a - bq, K2);
            float den_cs = fmaf(0.5f, a + bq, K2 + EPSV);
            float num_l  = fmaf(0.5f, q[j] - rr[j], K1);
            float den_l  = fmaf(0.5f, q[j] + rr[j], K1 + EPSV);
            // l > 0 always: relu(cs)*l == relu(l*cs) -> single divide
            lsum += fmaxf(__fdividef(num_cs * num_l, den_cs * den_l), 0.0f);
        }
    }
    return lsum;
}

__global__ __launch_bounds__(NTHREADS, 4)
void ssim_main_kernel(const float* __restrict__ X, const float* __restrict__ Y) {
    extern __shared__ __align__(16) unsigned char smem_raw[];
    u64* sM = (u64*)smem_raw;        // [IW][PS] packed (mu_s, mu_d)
    u64* sE = sM + IW * PS;          // [IW][PS] packed (E[s^2], E[d^2])

    const int tid = threadIdx.x;
    const int img = blockIdx.z;              // b*3 + ch
    const int b = img / NCH;
    const int ox0 = blockIdx.x * TW;
    const int oy0 = blockIdx.y * TH;
    const float* Xp = X + (size_t)img * IMG_H * IMG_W;
    const float* Yp = Y + (size_t)img * IMG_H * IMG_W;

    const bool edge = (blockIdx.x == gridDim.x - 1) || (blockIdx.y == gridDim.y - 1);
    float lsum = edge ? ssim_tile<true >(Xp, Yp, sM, sE, ox0, oy0, tid)
                      : ssim_tile<false>(Xp, Yp, sM, sE, ox0, oy0, tid);

    // ---- block reduction ----
    #pragma unroll
    for (int off = 16; off > 0; off >>= 1)
        lsum += __shfl_down_sync(0xffffffffu, lsum, off);

    float* red = (float*)smem_raw;   // aliases sM (dead after pass 2)
    int lane = tid & 31, wid = tid >> 5;
    __syncthreads();
    if (lane == 0) red[wid] = lsum;
    __syncthreads();
    if (tid == 0) {
        float s = 0.f;
        #pragma unroll
        for (int i = 0; i < NTHREADS / 32; i++) s += red[i];
        atomicAdd(&g_acc[b], s);
    }
}

extern "C" void kernel_launch(void* const* d_in, const int* in_sizes, int n_in,
                              void* d_out, int out_size) {
    const float* X = (const float*)d_in[0];
    const float* Y = (const float*)d_in[1];
    (void)in_sizes; (void)n_in; (void)out_size;

    cudaFuncSetAttribute(ssim_main_kernel,
                         cudaFuncAttributeMaxDynamicSharedMemorySize,
                         SMEM_BYTES);

    // keep main at launch position 3 (ncu capture lands there)
    ssim_zero_kernel<<<1, 32>>>();       // 0
    ssim_dummy1_kernel<<<1, 32>>>();     // 1
    ssim_dummy2_kernel<<<1, 32>>>();     // 2
    dim3 grid((OUT_W + TW - 1) / TW,     // 12
              (OUT_H + TH - 1) / TH,     // 24
              NBATCH * NCH);             // 48
    ssim_main_kernel<<<grid, NTHREADS, SMEM_BYTES>>>(X, Y);  // 3
    ssim_finalize_kernel<<<1, 32>>>((float*)d_out);          // 4
    ssim_dummy3_kernel<<<1, 32>>>();     // 5
}